// round 17
// baseline (speedup 1.0000x reference)
#include <cuda_runtime.h>
#include <cuda_fp16.h>
#include <math.h>

#define Bc 2
#define Sc 2048
#define Dc 1024
#define Hc 8
#define HDc 128
#define Mc (Bc*Sc)   // 4096

// fp16 scratch: Q,K as [B,H,S,HD]; V as [B,H,HD,S] (transposed)
__device__ __half g_Qh[Bc*Hc*Sc*HDc];
__device__ __half g_Kh[Bc*Hc*Sc*HDc];
__device__ __half g_Vh[Bc*Hc*Sc*HDc];
// fp16 inputs (flat [m][k]) and weights TRANSPOSED [n][k]
__device__ __half g_qh[Mc*Dc];
__device__ __half g_kh[Mc*Dc];
__device__ __half g_vh[Mc*Dc];
__device__ __half g_wqh[Dc*Dc];
__device__ __half g_wkh[Dc*Dc];
__device__ __half g_wvh[Dc*Dc];
// byte-packed mask (nonzero -> 1)
__device__ unsigned char g_mb[Bc*Sc*Sc];

__device__ __forceinline__ void mma16(float* c,
    unsigned a0, unsigned a1, unsigned a2, unsigned a3,
    unsigned b0, unsigned b1)
{
    asm volatile(
        "mma.sync.aligned.m16n8k16.row.col.f32.f16.f16.f32 "
        "{%0,%1,%2,%3}, {%4,%5,%6,%7}, {%8,%9}, {%0,%1,%2,%3};"
        : "+f"(c[0]), "+f"(c[1]), "+f"(c[2]), "+f"(c[3])
        : "r"(a0), "r"(a1), "r"(a2), "r"(a3), "r"(b0), "r"(b1));
}

__device__ __forceinline__ void ldsm4(unsigned& r0, unsigned& r1, unsigned& r2, unsigned& r3,
                                      unsigned addr)
{
    asm volatile("ldmatrix.sync.aligned.m8n8.x4.shared.b16 {%0,%1,%2,%3}, [%4];"
        : "=r"(r0), "=r"(r1), "=r"(r2), "=r"(r3) : "r"(addr));
}

__device__ __forceinline__ void cpa16(unsigned dst, const void* src) {
    asm volatile("cp.async.cg.shared.global [%0], [%1], 16;" :: "r"(dst), "l"(src));
}
#define CP_COMMIT() asm volatile("cp.async.commit_group;")
#define CP_WAIT1()  asm volatile("cp.async.wait_group 1;")
#define CP_WAIT0()  asm volatile("cp.async.wait_group 0;")

// ------------------------------------------------------------------
// maskpack: uint32 bool -> packed bytes (nonzero -> 1)
// ------------------------------------------------------------------
__global__ __launch_bounds__(256) void maskpack_kernel(const unsigned int* __restrict__ m)
{
    size_t i = ((size_t)blockIdx.x * 256 + threadIdx.x) * 16;
    uint4 a0 = *(const uint4*)(m + i);
    uint4 a1 = *(const uint4*)(m + i + 4);
    uint4 a2 = *(const uint4*)(m + i + 8);
    uint4 a3 = *(const uint4*)(m + i + 12);
    unsigned p0 = (a0.x?1u:0u) | (a0.y?0x100u:0u) | (a0.z?0x10000u:0u) | (a0.w?0x1000000u:0u);
    unsigned p1 = (a1.x?1u:0u) | (a1.y?0x100u:0u) | (a1.z?0x10000u:0u) | (a1.w?0x1000000u:0u);
    unsigned p2 = (a2.x?1u:0u) | (a2.y?0x100u:0u) | (a2.z?0x10000u:0u) | (a2.w?0x1000000u:0u);
    unsigned p3 = (a3.x?1u:0u) | (a3.y?0x100u:0u) | (a3.z?0x10000u:0u) | (a3.w?0x1000000u:0u);
    uint4 o = {p0, p1, p2, p3};
    *(uint4*)(g_mb + i) = o;
}

// ------------------------------------------------------------------
// cvt: fp32 -> fp16 for q,k,v
// ------------------------------------------------------------------
__global__ __launch_bounds__(256) void cvt_kernel(
    const float* __restrict__ q, const float* __restrict__ k, const float* __restrict__ v)
{
    const float* src; __half* dst;
    switch (blockIdx.y) {
        case 0: src = q; dst = g_qh; break;
        case 1: src = k; dst = g_kh; break;
        default: src = v; dst = g_vh; break;
    }
    size_t idx = ((size_t)blockIdx.x * 256 + threadIdx.x) * 8;
    float4 v0 = *(const float4*)(src + idx);
    float4 v1 = *(const float4*)(src + idx + 4);
    __half2 h0 = __floats2half2_rn(v0.x, v0.y);
    __half2 h1 = __floats2half2_rn(v0.z, v0.w);
    __half2 h2 = __floats2half2_rn(v1.x, v1.y);
    __half2 h3 = __floats2half2_rn(v1.z, v1.w);
    uint4 o = {*(unsigned*)&h0, *(unsigned*)&h1, *(unsigned*)&h2, *(unsigned*)&h3};
    *(uint4*)(dst + idx) = o;
}

// cvtT: fp16-round + transpose W -> Wt[n][k]
__global__ __launch_bounds__(256) void cvtT_kernel(
    const float* __restrict__ Wq, const float* __restrict__ Wk, const float* __restrict__ Wv)
{
    __shared__ float tile[32][33];
    const float* src; __half* dst;
    switch (blockIdx.z) {
        case 0: src = Wq; dst = g_wqh; break;
        case 1: src = Wk; dst = g_wkh; break;
        default: src = Wv; dst = g_wvh; break;
    }
    int x0 = blockIdx.x * 32, y0 = blockIdx.y * 32;
    int tx = threadIdx.x & 31, ty = threadIdx.x >> 5;
    #pragma unroll
    for (int j = 0; j < 32; j += 8)
        tile[ty + j][tx] = src[(size_t)(y0 + ty + j) * Dc + x0 + tx];
    __syncthreads();
    #pragma unroll
    for (int j = 0; j < 32; j += 8)
        dst[(size_t)(x0 + ty + j) * Dc + y0 + tx] = __float2half_rn(tile[tx][ty + j]);
}

// ------------------------------------------------------------------
// Projection GEMM (fp16 m16n8k16) — unchanged.
// ------------------------------------------------------------------
#define PSTRB 144
#define ABUFB (128 * PSTRB)
#define PSMB_B (2 * ABUFB)
#define PROJ_SMEM_BYTES (4 * ABUFB)

__global__ __launch_bounds__(256, 2) void proj_kernel(
    const float* __restrict__ bq, const float* __restrict__ bk, const float* __restrict__ bv)
{
    extern __shared__ char psm[];

    const __half* A; const __half* Wt; const float* bias; __half* out;
    if (blockIdx.z == 0)      { A = g_qh; Wt = g_wqh; bias = bq; out = g_Qh; }
    else if (blockIdx.z == 1) { A = g_kh; Wt = g_wkh; bias = bk; out = g_Kh; }
    else                      { A = g_vh; Wt = g_wvh; bias = bv; out = g_Vh; }

    const int tid  = threadIdx.x;
    const int warp = tid >> 5;
    const int lane = tid & 31;
    const int g    = lane >> 2;
    const int t    = lane & 3;

    const int m0 = blockIdx.y * 128;
    const int n0 = blockIdx.x * 128;
    const int wm = (warp & 3) * 32;
    const int wn = (warp >> 2) * 64;

    const unsigned sbase = (unsigned)__cvta_generic_to_shared(psm);
    const unsigned aB0 = sbase + (unsigned)((wm + (lane & 15)) * PSTRB + (lane >> 4) * 16);
    const unsigned bB0 = sbase + (unsigned)(PSMB_B + (wn + (lane & 15)) * PSTRB + (lane >> 4) * 16);

    auto prefA = [&](int it, int buf) {
        const __half* src = A + (size_t)m0 * Dc + it * 64;
        unsigned dstb = sbase + (unsigned)(buf * ABUFB);
        #pragma unroll
        for (int i = 0; i < 4; i++) {
            int idx = tid + 256 * i;
            int r = idx >> 3, c = idx & 7;
            cpa16(dstb + (unsigned)(r * PSTRB + c * 16), src + (size_t)r * Dc + c * 8);
        }
    };
    auto prefB = [&](int it, int buf) {
        const __half* src = Wt + (size_t)n0 * Dc + it * 64;
        unsigned dstb = sbase + (unsigned)(PSMB_B + buf * ABUFB);
        #pragma unroll
        for (int i = 0; i < 4; i++) {
            int idx = tid + 256 * i;
            int r = idx >> 3, c = idx & 7;
            cpa16(dstb + (unsigned)(r * PSTRB + c * 16), src + (size_t)r * Dc + c * 8);
        }
    };

    float C[2][8][4] = {};

    prefA(0, 0); prefB(0, 0); CP_COMMIT();

    for (int it = 0; it < 16; it++) {
        CP_WAIT0();
        __syncthreads();
        if (it + 1 < 16) {
            prefA(it + 1, (it + 1) & 1);
            prefB(it + 1, (it + 1) & 1);
            CP_COMMIT();
        }
        const int buf = it & 1;
        const unsigned aBase = aB0 + (unsigned)(buf * ABUFB);
        const unsigned bBase = bB0 + (unsigned)(buf * ABUFB);

        #pragma unroll
        for (int ks = 0; ks < 4; ks++) {
            unsigned a[2][4];
            #pragma unroll
            for (int mi = 0; mi < 2; mi++)
                ldsm4(a[mi][0], a[mi][1], a[mi][2], a[mi][3],
                      aBase + (unsigned)(mi * 16 * PSTRB + ks * 32));
            #pragma unroll
            for (int nb = 0; nb < 4; nb++) {
                unsigned b0, b1, b2, b3;
                ldsm4(b0, b1, b2, b3, bBase + (unsigned)(nb * 16 * PSTRB + ks * 32));
                #pragma unroll
                for (int mi = 0; mi < 2; mi++) {
                    mma16(C[mi][nb * 2],     a[mi][0], a[mi][1], a[mi][2], a[mi][3], b0, b2);
                    mma16(C[mi][nb * 2 + 1], a[mi][0], a[mi][1], a[mi][2], a[mi][3], b1, b3);
                }
            }
        }
        __syncthreads();
    }

    const int h = blockIdx.x;
    if (blockIdx.z != 2) {
        #pragma unroll
        for (int mi = 0; mi < 2; mi++) {
            int row0 = m0 + wm + mi * 16 + g;
            #pragma unroll
            for (int ni = 0; ni < 8; ni++) {
                int col = wn + ni * 8 + 2 * t;
                float b0v = bias[n0 + col], b1v = bias[n0 + col + 1];
                int bb0 = row0 >> 11, s0 = row0 & (Sc - 1);
                __half2 o0 = __floats2half2_rn(C[mi][ni][0] + b0v, C[mi][ni][1] + b1v);
                *(__half2*)(out + (((size_t)(bb0 * Hc + h)) * Sc + s0) * HDc + col) = o0;
                int r1 = row0 + 8;
                int bb1 = r1 >> 11, s1 = r1 & (Sc - 1);
                __half2 o1 = __floats2half2_rn(C[mi][ni][2] + b0v, C[mi][ni][3] + b1v);
                *(__half2*)(out + (((size_t)(bb1 * Hc + h)) * Sc + s1) * HDc + col) = o1;
            }
        }
    } else {
        #pragma unroll
        for (int mi = 0; mi < 2; mi++) {
            int row0 = m0 + wm + mi * 16 + g;
            #pragma unroll
            for (int ni = 0; ni < 8; ni++) {
                int col = wn + ni * 8 + 2 * t;
                float b0v = bias[n0 + col], b1v = bias[n0 + col + 1];
                int bb0 = row0 >> 11, s0 = row0 & (Sc - 1);
                __half* base0 = out + ((size_t)(bb0 * Hc + h)) * HDc * Sc;
                base0[(size_t)col * Sc + s0]       = __float2half_rn(C[mi][ni][0] + b0v);
                base0[(size_t)(col + 1) * Sc + s0] = __float2half_rn(C[mi][ni][1] + b1v);
                int r1 = row0 + 8;
                int bb1 = r1 >> 11, s1 = r1 & (Sc - 1);
                __half* base1 = out + ((size_t)(bb1 * Hc + h)) * HDc * Sc;
                base1[(size_t)col * Sc + s1]       = __float2half_rn(C[mi][ni][2] + b0v);
                base1[(size_t)(col + 1) * Sc + s1] = __float2half_rn(C[mi][ni][3] + b1v);
            }
        }
    }
}

// ------------------------------------------------------------------
// Flash attention FA2, TQ=64, 128 threads, Q in registers.
// exp2-domain softmax, ushort mask loads, fp32-sum l, 3 CTAs/SM target.
// ------------------------------------------------------------------
#define QSTRB  272
#define KSTRB  272
#define VSTRB  144
#define MROWB  80
#define ATHREADS 128

#define SMB_Q    0
#define SMB_K    (64 * QSTRB)             // 17408
#define SMB_VT   (SMB_K + 64 * KSTRB)     // 34816
#define SMB_MSK  (SMB_VT + 128 * VSTRB)   // 53248
#define ATTN_SMEM_BYTES (SMB_MSK + 64 * MROWB)   // 58368

#define NTILE (Sc / 64)

__global__ __launch_bounds__(ATHREADS, 3) void attn_kernel(float* __restrict__ out)
{
    extern __shared__ char smem[];
    const unsigned char* sMskB = (const unsigned char*)(smem + SMB_MSK);

    const int tid  = threadIdx.x;
    const int warp = tid >> 5;
    const int lane = tid & 31;
    const int g    = lane >> 2;
    const int t    = lane & 3;

    const int bh = blockIdx.y;
    const int b  = bh >> 3;
    const int h  = bh & (Hc - 1);
    const int q0 = blockIdx.x * 64;

    const int rw = warp * 16;

    const __half* Qg = g_Qh + (size_t)bh * Sc * HDc;
    const __half* Kg = g_Kh + (size_t)bh * Sc * HDc;
    const __half* Vg = g_Vh + (size_t)bh * HDc * Sc;
    const unsigned char* maskb = g_mb + (size_t)b * Sc * Sc;

    const unsigned sbase = (unsigned)__cvta_generic_to_shared(smem);
    const unsigned aQ = sbase + (unsigned)(SMB_Q  + (rw + (lane & 15)) * QSTRB + (lane >> 4) * 16);
    const unsigned bK = sbase + (unsigned)(SMB_K  + (lane & 15) * KSTRB + (lane >> 4) * 16);
    const unsigned bV = sbase + (unsigned)(SMB_VT + (lane & 15) * VSTRB + (lane >> 4) * 16);

    auto prefK = [&](int kt) {
        const __half* src = Kg + (size_t)kt * 64 * HDc;
        #pragma unroll
        for (int i = 0; i < 8; i++) {
            int idx = tid + ATHREADS * i;
            int r = idx >> 4, c = idx & 15;
            cpa16(sbase + (unsigned)(SMB_K + r * KSTRB + c * 16), src + (size_t)r * HDc + c * 8);
        }
    };
    auto prefV = [&](int kt) {
        const __half* src = Vg + kt * 64;
        #pragma unroll
        for (int i = 0; i < 8; i++) {
            int idx = tid + ATHREADS * i;
            int d = idx >> 3, c = idx & 7;
            cpa16(sbase + (unsigned)(SMB_VT + d * VSTRB + c * 16), src + (size_t)d * Sc + c * 8);
        }
    };
    auto prefM = [&](int kt) {
        const unsigned char* src = maskb + (size_t)q0 * Sc + kt * 64;
        #pragma unroll
        for (int i = 0; i < 2; i++) {
            int idx = tid + ATHREADS * i;
            int r = idx >> 2, c16 = (idx & 3) << 4;
            cpa16(sbase + (unsigned)(SMB_MSK + r * MROWB + c16), src + (size_t)r * Sc + c16);
        }
    };

    #pragma unroll
    for (int i = 0; i < 8; i++) {
        int idx = tid + ATHREADS * i;
        int r = idx >> 4, c = idx & 15;
        *(uint4*)(smem + SMB_Q + r * QSTRB + c * 16) =
            *(const uint4*)(Qg + (size_t)(q0 + r) * HDc + c * 8);
    }

    prefK(0); prefM(0); CP_COMMIT();
    prefV(0); CP_COMMIT();

    __syncthreads();
    unsigned qa[8][4];
    #pragma unroll
    for (int ks = 0; ks < 8; ks++)
        ldsm4(qa[ks][0], qa[ks][1], qa[ks][2], qa[ks][3], aQ + (unsigned)(ks * 32));

    float O[16][4] = {};
    float m0r = -1e30f, m1r = -1e30f;   // exp2-domain running max
    float l0r = 0.0f,   l1r = 0.0f;
    // scale * log2(e): softmax in exp2 domain (mathematically identical)
    const float scl2 = 0.08838834764831845f * 1.4426950408889634f;
    const int r0 = rw + g;

    for (int kt = 0; kt < NTILE; kt++) {
        const int ktn = (kt + 1 < NTILE) ? kt + 1 : NTILE - 1;

        CP_WAIT1();
        __syncthreads();

        // ---- QK^T ----
        float S[8][4] = {};
        #pragma unroll
        for (int ks = 0; ks < 8; ks++) {
            #pragma unroll
            for (int nb = 0; nb < 4; nb++) {
                unsigned b0, b1, b2, b3;
                ldsm4(b0, b1, b2, b3, bK + (unsigned)(nb * 16 * KSTRB + ks * 32));
                mma16(S[nb * 2],     qa[ks][0], qa[ks][1], qa[ks][2], qa[ks][3], b0, b2);
                mma16(S[nb * 2 + 1], qa[ks][0], qa[ks][1], qa[ks][2], qa[ks][3], b1, b3);
            }
        }

        // ---- mask + scale(exp2 domain), warp-local row max ----
        float mx0 = -1e30f, mx1 = -1e30f;
        #pragma unroll
        for (int ni = 0; ni < 8; ni++) {
            int col = ni * 8 + 2 * t;
            unsigned short mp0 = *(const unsigned short*)(sMskB + r0 * MROWB + col);
            unsigned short mp1 = *(const unsigned short*)(sMskB + (r0 + 8) * MROWB + col);
            float v0 = ((mp0 & 0xFFu)  ? -1e6f : S[ni][0]) * scl2;
            float v1 = ((mp0 >> 8)     ? -1e6f : S[ni][1]) * scl2;
            float v2 = ((mp1 & 0xFFu)  ? -1e6f : S[ni][2]) * scl2;
            float v3 = ((mp1 >> 8)     ? -1e6f : S[ni][3]) * scl2;
            S[ni][0] = v0; S[ni][1] = v1; S[ni][2] = v2; S[ni][3] = v3;
            mx0 = fmaxf(mx0, fmaxf(v0, v1));
            mx1 = fmaxf(mx1, fmaxf(v2, v3));
        }
        mx0 = fmaxf(mx0, __shfl_xor_sync(0xffffffffu, mx0, 1, 4));
        mx0 = fmaxf(mx0, __shfl_xor_sync(0xffffffffu, mx0, 2, 4));
        mx1 = fmaxf(mx1, __shfl_xor_sync(0xffffffffu, mx1, 1, 4));
        mx1 = fmaxf(mx1, __shfl_xor_sync(0xffffffffu, mx1, 2, 4));

        // ---- exp2 in regs; fp32 sums; pack P as A-fragments ----
        float mnew0 = fmaxf(m0r, mx0), mnew1 = fmaxf(m1r, mx1);
        unsigned ph[8][2];
        float s0 = 0.0f, s1 = 0.0f;
        #pragma unroll
        for (int ni = 0; ni < 8; ni++) {
            float e0 = exp2f(S[ni][0] - mnew0);
            float e1 = exp2f(S[ni][1] - mnew0);
            float e2 = exp2f(S[ni][2] - mnew1);
            float e3 = exp2f(S[ni][3] - mnew1);
            s0 += e0 + e1;
            s1 += e2 + e3;
            __half2 p0 = __floats2half2_rn(e0, e1);
            __half2 p1 = __floats2half2_rn(e2, e3);
            ph[ni][0] = *(unsigned*)&p0;
            ph[ni][1] = *(unsigned*)&p1;
        }
        s0 += __shfl_xor_sync(0xffffffffu, s0, 1, 4);
        s0 += __shfl_xor_sync(0xffffffffu, s0, 2, 4);
        s1 += __shfl_xor_sync(0xffffffffu, s1, 1, 4);
        s1 += __shfl_xor_sync(0xffffffffu, s1, 2, 4);
        float a0f = exp2f(m0r - mnew0);
        float a1f = exp2f(m1r - mnew1);
        l0r = l0r * a0f + s0;
        l1r = l1r * a1f + s1;
        m0r = mnew0;
        m1r = mnew1;

        __syncthreads();
        prefK(ktn); prefM(ktn); CP_COMMIT();

        CP_WAIT1();
        __syncthreads();

        // ---- O rescale + PV ----
        #pragma unroll
        for (int ni = 0; ni < 16; ni++) {
            O[ni][0] *= a0f; O[ni][1] *= a0f;
            O[ni][2] *= a1f; O[ni][3] *= a1f;
        }
        #pragma unroll
        for (int ks = 0; ks < 4; ks++) {
            unsigned pa0 = ph[2 * ks][0];
            unsigned pa1 = ph[2 * ks][1];
            unsigned pa2 = ph[2 * ks + 1][0];
            unsigned pa3 = ph[2 * ks + 1][1];
            #pragma unroll
            for (int nb = 0; nb < 8; nb++) {
                unsigned b0, b1, b2, b3;
                ldsm4(b0, b1, b2, b3, bV + (unsigned)(nb * 16 * VSTRB + ks * 32));
                mma16(O[nb * 2],     pa0, pa1, pa2, pa3, b0, b2);
                mma16(O[nb * 2 + 1], pa0, pa1, pa2, pa3, b1, b3);
            }
        }
        __syncthreads();

        prefV(ktn); CP_COMMIT();
    }

    CP_WAIT0();

    {
        float linv0 = 1.0f / l0r;
        float linv1 = 1.0f / l1r;
        int row0 = q0 + rw + g;
        #pragma unroll
        for (int ni = 0; ni < 16; ni++) {
            int col = ni * 8 + 2 * t;
            float* d0 = out + ((size_t)b * Sc + row0) * Dc + h * HDc + col;
            *(float2*)d0 = make_float2(O[ni][0] * linv0, O[ni][1] * linv0);
            float* d1 = out + ((size_t)b * Sc + row0 + 8) * Dc + h * HDc + col;
            *(float2*)d1 = make_float2(O[ni][2] * linv1, O[ni][3] * linv1);
        }
    }
}

// ------------------------------------------------------------------
extern "C" void kernel_launch(void* const* d_in, const int* in_sizes, int n_in,
                              void* d_out, int out_size)
{
    const float* q  = (const float*)d_in[0];
    const float* k  = (const float*)d_in[1];
    const float* v  = (const float*)d_in[2];
    const unsigned int* mask = (const unsigned int*)d_in[3];
    const float* Wq = (const float*)d_in[4];
    const float* bq = (const float*)d_in[5];
    const float* Wk = (const float*)d_in[6];
    const float* bk = (const float*)d_in[7];
    const float* Wv = (const float*)d_in[8];
    const float* bv = (const float*)d_in[9];
    float* out = (float*)d_out;

    maskpack_kernel<<<(Bc * Sc * Sc) / 16 / 256, 256>>>(mask);
    dim3 cgrid(Mc * Dc / 8 / 256, 3);
    cvt_kernel<<<cgrid, 256>>>(q, k, v);
    dim3 tgrid(Dc / 32, Dc / 32, 3);
    cvtT_kernel<<<tgrid, 256>>>(Wq, Wk, Wv);

    cudaFuncSetAttribute(proj_kernel,
                         cudaFuncAttributeMaxDynamicSharedMemorySize,
                         PROJ_SMEM_BYTES);
    dim3 pgrid(Dc / 128, Mc / 128, 3);
    proj_kernel<<<pgrid, 256, PROJ_SMEM_BYTES>>>(bq, bk, bv);

    cudaFuncSetAttribute(attn_kernel,
                         cudaFuncAttributeMaxDynamicSharedMemorySize,
                         ATTN_SMEM_BYTES);
    dim3 agrid(Sc / 64, Bc * Hc);
    attn_kernel<<<agrid, ATHREADS, ATTN_SMEM_BYTES>>>(out);
}